// round 4
// baseline (speedup 1.0000x reference)
#include <cuda_runtime.h>
#include <cuda_fp16.h>
#include <stdint.h>

#define N_OUT  11008
#define K_TOT  4096
#define M_TOK  64
#define HIGH_K 1024
#define NT     64      // output columns per CTA
#define KC     64      // K per chunk
#define NCHUNK 64
#define THREADS 512

// SMEM: 4-stage ring of {A fp16 swizzled 8KB, W packed 12KB, scales 512B} + B tile 8KB
#define ASZ 8192
#define WSZ 12288
#define SSZ 512
#define STG (ASZ + WSZ + SSZ)        // 20992
#define SM_B (4 * STG)               // 83968
#define SMEM_BYTES (SM_B + 8192)     // 92160

__device__ __half g_xp[M_TOK * K_TOT];   // permuted x in fp16 (scratch, 512KB)

__device__ __forceinline__ uint32_t smem_u32(const void* p) {
    uint32_t a;
    asm("{ .reg .u64 t; cvta.to.shared.u64 t, %1; cvt.u32.u64 %0, t; }" : "=r"(a) : "l"(p));
    return a;
}
__device__ __forceinline__ uint32_t swz(uint32_t o) { return o ^ ((o >> 3) & 0x70); }

__device__ __forceinline__ void cp16(uint32_t dst, const void* src) {
    asm volatile("cp.async.cg.shared.global [%0], [%1], 16;" :: "r"(dst), "l"(src));
}
__device__ __forceinline__ void cp_commit() {
    asm volatile("cp.async.commit_group;" ::: "memory");
}
__device__ __forceinline__ void cp_wait2() {
    asm volatile("cp.async.wait_group 2;" ::: "memory");
}

__device__ __forceinline__ void ldm_x4(uint32_t& r0, uint32_t& r1, uint32_t& r2, uint32_t& r3,
                                       uint32_t addr) {
    asm volatile("ldmatrix.sync.aligned.m8n8.x4.shared.b16 {%0,%1,%2,%3}, [%4];"
                 : "=r"(r0), "=r"(r1), "=r"(r2), "=r"(r3) : "r"(addr));
}
__device__ __forceinline__ void mma16816(float& c0, float& c1, float& c2, float& c3,
                                         uint32_t a0, uint32_t a1, uint32_t a2, uint32_t a3,
                                         uint32_t b0, uint32_t b1) {
    asm volatile("mma.sync.aligned.m16n8k16.row.col.f32.f16.f16.f32 "
                 "{%0,%1,%2,%3}, {%4,%5,%6,%7}, {%8,%9}, {%0,%1,%2,%3};"
                 : "+f"(c0), "+f"(c1), "+f"(c2), "+f"(c3)
                 : "r"(a0), "r"(a1), "r"(a2), "r"(a3), "r"(b0), "r"(b1));
}

// ---------------- prep: x_perm -> fp16 ----------------
__global__ void prep_kernel(const float* __restrict__ x, const int* __restrict__ ci) {
    int idx = blockIdx.x * blockDim.x + threadIdx.x;   // 64*4096 threads exactly
    int m = idx >> 12;
    int k = idx & 4095;
    g_xp[idx] = __float2half_rn(x[(m << 12) + ci[k]]);
}

// ---------------- main fused dequant + mma.sync GEMM ----------------
__global__ void __launch_bounds__(THREADS, 2) gemm_kernel(
    const int* __restrict__ Wh, const int* __restrict__ Wl,
    const float* __restrict__ sh, const float* __restrict__ sl,
    const float* __restrict__ bias, float* __restrict__ out)
{
    extern __shared__ char smem[];
    const uint32_t sb = smem_u32(smem);
    const int tid = threadIdx.x;
    const int n0 = blockIdx.x * NT;

    const int lane = tid & 31;
    const int wid  = tid >> 5;          // 0..15
    const int wm   = wid & 3;           // warp m-tile (16 rows)
    const int wn   = wid >> 2;          // warp n-tile (16 cols)

    // ldmatrix per-lane base offsets (unswizzled; swizzle applied per k-step)
    const int sub = lane >> 3;
    const uint32_t offA = (uint32_t)((wm * 16 + (sub & 1) * 8 + (lane & 7)) * 128 + (sub >> 1) * 16);
    const uint32_t offB = (uint32_t)((wn * 16 + (sub >> 1) * 8 + (lane & 7)) * 128 + (sub & 1) * 16);

    // work split for staging + dequant
    const int arow = tid >> 3;          // A cp.async: row 0..63
    const int akb  = tid & 7;           // A cp.async: 16B block
    const int bn   = tid & 63;          // dequant: local col
    const int wr0  = tid >> 4;          // W cp.async: row (first batch)
    const int wg0  = tid & 15;          // W cp.async: 16B granule in row

    // ---- stage issuer (cp.async, no commit) ----
    auto issue_stage = [&](int cn) {
        const uint32_t slot = sb + (uint32_t)((cn & 3) * STG);
        const int k0 = cn * KC;
        // A chunk: 512 x 16B, stored pre-swizzled
        cp16(slot + swz((uint32_t)(arow * 128 + akb * 16)),
             g_xp + (arow << 12) + k0 + (akb << 3));
        const uint32_t wb = slot + ASZ;
        if (cn < 16) {
            const int* src = Wh + 48 * cn * N_OUT + n0;
            cp16(wb + wr0 * 256 + wg0 * 16, src + wr0 * N_OUT + wg0 * 4);
            if (tid < 256) {
                int t = tid + 512;
                cp16(wb + (t >> 4) * 256 + (t & 15) * 16, src + (t >> 4) * N_OUT + (t & 15) * 4);
            }
            if (tid < 16)
                cp16(slot + ASZ + WSZ + tid * 16, sh + (k0 >> 7) * N_OUT + n0 + tid * 4);
        } else {
            const int* src = Wl + 40 * (cn - 16) * N_OUT + n0;
            cp16(wb + wr0 * 256 + wg0 * 16, src + wr0 * N_OUT + wg0 * 4);
            if (tid < 128) {
                int t = tid + 512;
                cp16(wb + (t >> 4) * 256 + (t & 15) * 16, src + (t >> 4) * N_OUT + (t & 15) * 4);
            }
            if (tid < 16)
                cp16(slot + ASZ + WSZ + tid * 16,
                     sl + ((k0 - HIGH_K) >> 7) * N_OUT + n0 + tid * 4);
        }
    };

    float acc[2][4];
    #pragma unroll
    for (int t = 0; t < 2; ++t)
        #pragma unroll
        for (int i = 0; i < 4; ++i) acc[t][i] = 0.0f;

    // prologue: 3 stages in flight
    issue_stage(0); cp_commit();
    issue_stage(1); cp_commit();
    issue_stage(2); cp_commit();

    for (int c = 0; c < NCHUNK; ++c) {
        const uint32_t slotOff = (uint32_t)((c & 3) * STG);

        cp_wait2();          // stage c arrived (<=2 younger groups pending)
        __syncthreads();     // visible to all; also: mma(c-1) reads fully done

        // issue stage c+3 early (overwrites slot (c-1)&3 — safe post-barrier)
        if (c + 3 < NCHUNK) issue_stage(c + 3);
        cp_commit();         // unconditional: keeps group counting uniform

        // ---- dequant packed W (SMEM) -> fp16 B tile ----
        const int* wp = (const int*)(smem + slotOff + ASZ);
        const float s = *(const float*)(smem + slotOff + ASZ + WSZ + bn * 4);
        if (c < 16) {  // 6-bit: two quads per thread
            const int qi0 = tid >> 6;
            {
                int w0 = wp[(3 * qi0 + 0) * 64 + bn];
                int w1 = wp[(3 * qi0 + 1) * 64 + bn];
                int w2 = wp[(3 * qi0 + 2) * 64 + bn];
                int v0 = w0 & 63;
                int v1 = ((w0 >> 6) & 3) | ((w1 & 15) << 2);
                int v2 = ((w1 >> 4) & 15) | ((w2 & 3) << 4);
                int v3 = (w2 >> 2) & 63;
                __half2 h01 = __floats2half2_rn((float)(v0 - 31) * s, (float)(v1 - 31) * s);
                __half2 h23 = __floats2half2_rn((float)(v2 - 31) * s, (float)(v3 - 31) * s);
                uint2 val;
                val.x = *reinterpret_cast<uint32_t*>(&h01);
                val.y = *reinterpret_cast<uint32_t*>(&h23);
                *(uint2*)(smem + SM_B + swz((uint32_t)(bn * 128 + qi0 * 8))) = val;
            }
            {
                int w0 = wp[(3 * qi0 + 24) * 64 + bn];
                int w1 = wp[(3 * qi0 + 25) * 64 + bn];
                int w2 = wp[(3 * qi0 + 26) * 64 + bn];
                int v0 = w0 & 63;
                int v1 = ((w0 >> 6) & 3) | ((w1 & 15) << 2);
                int v2 = ((w1 >> 4) & 15) | ((w2 & 3) << 4);
                int v3 = (w2 >> 2) & 63;
                __half2 h01 = __floats2half2_rn((float)(v0 - 31) * s, (float)(v1 - 31) * s);
                __half2 h23 = __floats2half2_rn((float)(v2 - 31) * s, (float)(v3 - 31) * s);
                uint2 val;
                val.x = *reinterpret_cast<uint32_t*>(&h01);
                val.y = *reinterpret_cast<uint32_t*>(&h23);
                *(uint2*)(smem + SM_B + swz((uint32_t)(bn * 128 + (qi0 + 8) * 8))) = val;
            }
        } else {       // 5-bit: one octet per thread
            const int oi = tid >> 6;
            int w0 = wp[(5 * oi + 0) * 64 + bn];
            int w1 = wp[(5 * oi + 1) * 64 + bn];
            int w2 = wp[(5 * oi + 2) * 64 + bn];
            int w3 = wp[(5 * oi + 3) * 64 + bn];
            int w4 = wp[(5 * oi + 4) * 64 + bn];
            int v0 = w0 & 31;
            int v1 = ((w0 >> 5) & 7) | ((w1 & 3) << 3);
            int v2 = (w1 >> 2) & 31;
            int v3 = ((w1 >> 7) & 1) | ((w2 & 15) << 1);
            int v4 = ((w2 >> 4) & 15) | ((w3 & 1) << 4);
            int v5 = (w3 >> 1) & 31;
            int v6 = ((w3 >> 6) & 3) | ((w4 & 7) << 2);
            int v7 = (w4 >> 3) & 31;
            __half2 p0 = __floats2half2_rn((float)(v0 - 15) * s, (float)(v1 - 15) * s);
            __half2 p1 = __floats2half2_rn((float)(v2 - 15) * s, (float)(v3 - 15) * s);
            __half2 p2 = __floats2half2_rn((float)(v4 - 15) * s, (float)(v5 - 15) * s);
            __half2 p3 = __floats2half2_rn((float)(v6 - 15) * s, (float)(v7 - 15) * s);
            uint4 val;
            val.x = *reinterpret_cast<uint32_t*>(&p0);
            val.y = *reinterpret_cast<uint32_t*>(&p1);
            val.z = *reinterpret_cast<uint32_t*>(&p2);
            val.w = *reinterpret_cast<uint32_t*>(&p3);
            *(uint4*)(smem + SM_B + swz((uint32_t)(bn * 128 + oi * 16))) = val;
        }
        __syncthreads();

        // ---- mma phase: A from ring slot, B from B tile ----
        #pragma unroll
        for (int ks = 0; ks < 4; ++ks) {
            uint32_t a0, a1, a2, a3, b0, b1, b2, b3;
            ldm_x4(a0, a1, a2, a3, sb + slotOff + swz(offA + (uint32_t)(ks * 32)));
            ldm_x4(b0, b1, b2, b3, sb + SM_B + swz(offB + (uint32_t)(ks * 32)));
            mma16816(acc[0][0], acc[0][1], acc[0][2], acc[0][3], a0, a1, a2, a3, b0, b1);
            mma16816(acc[1][0], acc[1][1], acc[1][2], acc[1][3], a0, a1, a2, a3, b2, b3);
        }
    }

    // ---- epilogue: acc regs -> gmem with bias ----
    const int r0 = wm * 16 + (lane >> 2);
    #pragma unroll
    for (int nt = 0; nt < 2; ++nt) {
        const int nb = n0 + wn * 16 + nt * 8 + (lane & 3) * 2;
        const float2 bb = *(const float2*)(bias + nb);
        float2 o;
        o.x = acc[nt][0] + bb.x;
        o.y = acc[nt][1] + bb.y;
        *(float2*)(out + r0 * N_OUT + nb) = o;
        o.x = acc[nt][2] + bb.x;
        o.y = acc[nt][3] + bb.y;
        *(float2*)(out + (r0 + 8) * N_OUT + nb) = o;
    }
}

extern "C" void kernel_launch(void* const* d_in, const int* in_sizes, int n_in,
                              void* d_out, int out_size) {
    const float* x    = (const float*)d_in[0];
    const int*   Wh   = (const int*)d_in[1];
    const int*   Wl   = (const int*)d_in[2];
    const float* sh   = (const float*)d_in[3];
    const float* sl   = (const float*)d_in[4];
    const int*   ci   = (const int*)d_in[5];
    const float* bias = (const float*)d_in[6];
    float* out = (float*)d_out;

    cudaFuncSetAttribute(gemm_kernel, cudaFuncAttributeMaxDynamicSharedMemorySize, SMEM_BYTES);

    prep_kernel<<<(M_TOK * K_TOT) / 256, 256>>>(x, ci);
    gemm_kernel<<<N_OUT / NT, THREADS, SMEM_BYTES>>>(Wh, Wl, sh, sl, bias, out);
}

// round 6
// speedup vs baseline: 1.2521x; 1.2521x over previous
#include <cuda_runtime.h>
#include <cuda_fp16.h>
#include <stdint.h>

#define N_OUT  11008
#define K_TOT  4096
#define M_TOK  64
#define HIGH_K 1024
#define NT     64      // output columns per CTA
#define KC     64      // K per chunk
#define CPC    32      // chunks per CTA (split-K = 2)
#define THREADS 512

// SMEM: 4-stage ring of {A fp16 swizzled 8KB, W packed 12KB, scales 512B} + B tile 8KB
#define ASZ 8192
#define WSZ 12288
#define SSZ 512
#define STG (ASZ + WSZ + SSZ)        // 20992
#define SM_B (4 * STG)               // 83968
#define SMEM_BYTES (SM_B + 8192)     // 92160

__device__ __half g_xp[M_TOK * K_TOT];     // permuted x in fp16 (512KB)
__device__ float  g_part[M_TOK * N_OUT];   // split-K partial (2.8MB)

__device__ __forceinline__ uint32_t smem_u32(const void* p) {
    uint32_t a;
    asm("{ .reg .u64 t; cvta.to.shared.u64 t, %1; cvt.u32.u64 %0, t; }" : "=r"(a) : "l"(p));
    return a;
}
__device__ __forceinline__ uint32_t swz(uint32_t o) { return o ^ ((o >> 3) & 0x70); }

__device__ __forceinline__ void cp16(uint32_t dst, const void* src) {
    asm volatile("cp.async.cg.shared.global [%0], [%1], 16;" :: "r"(dst), "l"(src));
}
__device__ __forceinline__ void cp_commit() {
    asm volatile("cp.async.commit_group;" ::: "memory");
}
__device__ __forceinline__ void cp_wait2() {
    asm volatile("cp.async.wait_group 2;" ::: "memory");
}

__device__ __forceinline__ void ldm_x4(uint32_t& r0, uint32_t& r1, uint32_t& r2, uint32_t& r3,
                                       uint32_t addr) {
    asm volatile("ldmatrix.sync.aligned.m8n8.x4.shared.b16 {%0,%1,%2,%3}, [%4];"
                 : "=r"(r0), "=r"(r1), "=r"(r2), "=r"(r3) : "r"(addr));
}
__device__ __forceinline__ void mma16816(float& c0, float& c1, float& c2, float& c3,
                                         uint32_t a0, uint32_t a1, uint32_t a2, uint32_t a3,
                                         uint32_t b0, uint32_t b1) {
    asm volatile("mma.sync.aligned.m16n8k16.row.col.f32.f16.f16.f32 "
                 "{%0,%1,%2,%3}, {%4,%5,%6,%7}, {%8,%9}, {%0,%1,%2,%3};"
                 : "+f"(c0), "+f"(c1), "+f"(c2), "+f"(c3)
                 : "r"(a0), "r"(a1), "r"(a2), "r"(a3), "r"(b0), "r"(b1));
}

// magic-number fp16 pair: u = 0x64006400 | v_lo | (v_hi<<16); (u - off) * s
__device__ __forceinline__ uint32_t dq2(uint32_t bits, uint32_t off, uint32_t s2) {
    uint32_t u = 0x64006400u | bits;
    __half2 h = __hsub2(*reinterpret_cast<__half2*>(&u),
                        *reinterpret_cast<const __half2*>(&off));
    h = __hmul2(h, *reinterpret_cast<const __half2*>(&s2));
    return *reinterpret_cast<uint32_t*>(&h);
}

// ---------------- prep: x_perm -> fp16 ----------------
__global__ void prep_kernel(const float* __restrict__ x, const int* __restrict__ ci) {
    int idx = blockIdx.x * blockDim.x + threadIdx.x;   // 64*4096 threads exactly
    int m = idx >> 12;
    int k = idx & 4095;
    g_xp[idx] = __float2half_rn(x[(m << 12) + ci[k]]);
}

// ---------------- reduce: out = out + part + bias ----------------
__global__ void reduce_kernel(float* __restrict__ out, const float* __restrict__ bias) {
    int n = blockIdx.x * blockDim.x + threadIdx.x;   // grid.x*256 == N_OUT
    int m = blockIdx.y;
    int i = m * N_OUT + n;
    out[i] = out[i] + g_part[i] + bias[n];
}

// ---------------- main fused dequant + mma.sync GEMM (split-K 2) ----------------
__global__ void __launch_bounds__(THREADS, 2) gemm_kernel(
    const int* __restrict__ Wh, const int* __restrict__ Wl,
    const float* __restrict__ sh, const float* __restrict__ sl,
    float* __restrict__ out)
{
    extern __shared__ char smem[];
    const uint32_t sb = smem_u32(smem);
    const int tid = threadIdx.x;
    const int n0 = blockIdx.x * NT;
    const int kh = blockIdx.y;          // k-half: 0 -> chunks 0..31, 1 -> 32..63
    const int cbase = kh * CPC;

    const int lane = tid & 31;
    const int wid  = tid >> 5;          // 0..15
    const int wm   = wid & 3;           // warp m-tile (16 rows)
    const int wn   = wid >> 2;          // warp n-tile (16 cols)

    const int sub = lane >> 3;
    const uint32_t offA = (uint32_t)((wm * 16 + (sub & 1) * 8 + (lane & 7)) * 128 + (sub >> 1) * 16);
    const uint32_t offB = (uint32_t)((wn * 16 + (sub >> 1) * 8 + (lane & 7)) * 128 + (sub & 1) * 16);

    // work split for staging + dequant
    const int arow = tid >> 3;          // A cp.async: row 0..63
    const int akb  = tid & 7;           // A cp.async: 16B block
    const int bn   = tid & 63;          // dequant: local col
    const int wr0  = tid >> 4;          // W cp.async: row (first batch)
    const int wg0  = tid & 15;          // W cp.async: 16B granule in row

    // ---- stage issuer (cp.async, no commit); cg = global chunk ----
    auto issue_stage = [&](int c) {
        const int cg = cbase + c;
        const uint32_t slot = sb + (uint32_t)((c & 3) * STG);
        const int k0 = cg * KC;
        cp16(slot + swz((uint32_t)(arow * 128 + akb * 16)),
             g_xp + (arow << 12) + k0 + (akb << 3));
        const uint32_t wb = slot + ASZ;
        if (cg < 16) {
            const int* src = Wh + 48 * cg * N_OUT + n0;
            cp16(wb + wr0 * 256 + wg0 * 16, src + wr0 * N_OUT + wg0 * 4);
            if (tid < 256) {
                int t = tid + 512;
                cp16(wb + (t >> 4) * 256 + (t & 15) * 16, src + (t >> 4) * N_OUT + (t & 15) * 4);
            }
            if (tid < 16)
                cp16(slot + ASZ + WSZ + tid * 16, sh + (k0 >> 7) * N_OUT + n0 + tid * 4);
        } else {
            const int* src = Wl + 40 * (cg - 16) * N_OUT + n0;
            cp16(wb + wr0 * 256 + wg0 * 16, src + wr0 * N_OUT + wg0 * 4);
            if (tid < 128) {
                int t = tid + 512;
                cp16(wb + (t >> 4) * 256 + (t & 15) * 16, src + (t >> 4) * N_OUT + (t & 15) * 4);
            }
            if (tid < 16)
                cp16(slot + ASZ + WSZ + tid * 16,
                     sl + ((k0 - HIGH_K) >> 7) * N_OUT + n0 + tid * 4);
        }
    };

    float acc[2][4];
    #pragma unroll
    for (int t = 0; t < 2; ++t)
        #pragma unroll
        for (int i = 0; i < 4; ++i) acc[t][i] = 0.0f;

    issue_stage(0); cp_commit();
    issue_stage(1); cp_commit();
    issue_stage(2); cp_commit();

    for (int c = 0; c < CPC; ++c) {
        const int cg = cbase + c;
        const uint32_t slotOff = (uint32_t)((c & 3) * STG);

        cp_wait2();
        __syncthreads();

        if (c + 3 < CPC) issue_stage(c + 3);
        cp_commit();

        // ---- dequant packed W (SMEM) -> fp16 B tile, magic-number path ----
        const int* wp = (const int*)(smem + slotOff + ASZ);
        const float sf = *(const float*)(smem + slotOff + ASZ + WSZ + bn * 4);
        const __half sh1 = __float2half_rn(sf);
        const __half2 sh2 = __half2half2(sh1);
        const uint32_t s2 = *reinterpret_cast<const uint32_t*>(&sh2);

        if (cg < 16) {  // 6-bit: two quads per thread; offset 1024+31 -> 0x641F
            const int qi0 = tid >> 6;
            #pragma unroll
            for (int half = 0; half < 2; ++half) {
                const int rb = 3 * qi0 + 24 * half;
                int w0 = wp[(rb + 0) * 64 + bn];
                int w1 = wp[(rb + 1) * 64 + bn];
                int w2 = wp[(rb + 2) * 64 + bn];
                uint32_t b01 = (w0 & 63) | ((w0 & 0xC0) << 10) | ((w1 & 15) << 18);
                uint32_t b23 = ((w1 >> 4) & 15) | ((w2 & 3) << 4) | ((w2 & 0xFC) << 14);
                uint2 val;
                val.x = dq2(b01, 0x641F641Fu, s2);
                val.y = dq2(b23, 0x641F641Fu, s2);
                *(uint2*)(smem + SM_B + swz((uint32_t)(bn * 128 + (qi0 + 8 * half) * 8))) = val;
            }
        } else {       // 5-bit: one octet per thread; offset 1024+15 -> 0x640F
            const int oi = tid >> 6;
            const int rb = 5 * oi;
            int w0 = wp[(rb + 0) * 64 + bn];
            int w1 = wp[(rb + 1) * 64 + bn];
            int w2 = wp[(rb + 2) * 64 + bn];
            int w3 = wp[(rb + 3) * 64 + bn];
            int w4 = wp[(rb + 4) * 64 + bn];
            uint32_t b01 = (w0 & 31) | ((w0 & 0xE0) << 11) | ((w1 & 3) << 19);
            uint32_t b23 = ((w1 >> 2) & 31) | ((w1 & 0x80) << 9) | ((w2 & 15) << 17);
            uint32_t b45 = ((w2 >> 4) & 15) | ((w3 & 1) << 4) | ((w3 & 0x3E) << 15);
            uint32_t b67 = ((w3 >> 6) & 3) | ((w4 & 7) << 2) | ((w4 & 0xF8) << 13);
            uint4 val;
            val.x = dq2(b01, 0x640F640Fu, s2);
            val.y = dq2(b23, 0x640F640Fu, s2);
            val.z = dq2(b45, 0x640F640Fu, s2);
            val.w = dq2(b67, 0x640F640Fu, s2);
            *(uint4*)(smem + SM_B + swz((uint32_t)(bn * 128 + oi * 16))) = val;
        }
        __syncthreads();

        // ---- mma phase: A from ring slot, B from B tile ----
        #pragma unroll
        for (int ks = 0; ks < 4; ++ks) {
            uint32_t a0, a1, a2, a3, b0, b1, b2, b3;
            ldm_x4(a0, a1, a2, a3, sb + slotOff + swz(offA + (uint32_t)(ks * 32)));
            ldm_x4(b0, b1, b2, b3, sb + SM_B + swz(offB + (uint32_t)(ks * 32)));
            mma16816(acc[0][0], acc[0][1], acc[0][2], acc[0][3], a0, a1, a2, a3, b0, b1);
            mma16816(acc[1][0], acc[1][1], acc[1][2], acc[1][3], a0, a1, a2, a3, b2, b3);
        }
    }

    // ---- epilogue: partials (no bias) -> out (kh=0) or g_part (kh=1) ----
    float* dst = kh ? g_part : out;
    const int r0 = wm * 16 + (lane >> 2);
    #pragma unroll
    for (int nt = 0; nt < 2; ++nt) {
        const int nb = n0 + wn * 16 + nt * 8 + (lane & 3) * 2;
        float2 o;
        o.x = acc[nt][0];
        o.y = acc[nt][1];
        *(float2*)(dst + r0 * N_OUT + nb) = o;
        o.x = acc[nt][2];
        o.y = acc[nt][3];
        *(float2*)(dst + (r0 + 8) * N_OUT + nb) = o;
    }
}

extern "C" void kernel_launch(void* const* d_in, const int* in_sizes, int n_in,
                              void* d_out, int out_size) {
    const float* x    = (const float*)d_in[0];
    const int*   Wh   = (const int*)d_in[1];
    const int*   Wl   = (const int*)d_in[2];
    const float* sh   = (const float*)d_in[3];
    const float* sl   = (const float*)d_in[4];
    const int*   ci   = (const int*)d_in[5];
    const float* bias = (const float*)d_in[6];
    float* out = (float*)d_out;

    cudaFuncSetAttribute(gemm_kernel, cudaFuncAttributeMaxDynamicSharedMemorySize, SMEM_BYTES);

    prep_kernel<<<(M_TOK * K_TOT) / 256, 256>>>(x, ci);
    gemm_kernel<<<dim3(N_OUT / NT, 2), THREADS, SMEM_BYTES>>>(Wh, Wl, sh, sl, out);
    reduce_kernel<<<dim3(N_OUT / 256, M_TOK), 256>>>(out, bias);
}

// round 8
// speedup vs baseline: 1.3349x; 1.0661x over previous
#include <cuda_runtime.h>
#include <cuda_fp16.h>
#include <stdint.h>

#define N_OUT  11008
#define K_TOT  4096
#define M_TOK  64
#define HIGH_K 1024
#define NT     64      // output columns per CTA
#define KC     64      // K per chunk
#define CPC    32      // chunks per CTA (split-K = 2)
#define THREADS 512

// SMEM layout
//   AB ring: 3 stages x 16KB  (A fp16 swizzled 8KB @+0, B fp16 swizzled 8KB @+8192)
//   RAW ring: 3 stages x 12544 (packed W 12288 @+0, scales 256B @+12288)
//   mbarriers: full[3], empty[3]
#define ABST   16384
#define RAW0   49152
#define RAWST  12544
#define MBAR   86784
#define SMEM_BYTES 87040

__device__ __half g_xp[M_TOK * K_TOT];     // permuted x in fp16 (512KB)
__device__ float  g_part[M_TOK * N_OUT];   // split-K partial (2.8MB)

__device__ __forceinline__ uint32_t smem_u32(const void* p) {
    uint32_t a;
    asm("{ .reg .u64 t; cvta.to.shared.u64 t, %1; cvt.u32.u64 %0, t; }" : "=r"(a) : "l"(p));
    return a;
}
__device__ __forceinline__ uint32_t swz(uint32_t o) { return o ^ ((o >> 3) & 0x70); }

__device__ __forceinline__ void cp16(uint32_t dst, const void* src) {
    asm volatile("cp.async.cg.shared.global [%0], [%1], 16;" :: "r"(dst), "l"(src));
}
__device__ __forceinline__ void cp_commit() {
    asm volatile("cp.async.commit_group;" ::: "memory");
}
__device__ __forceinline__ void cp_wait2() {
    asm volatile("cp.async.wait_group 2;" ::: "memory");
}
__device__ __forceinline__ void prod_bar() {
    asm volatile("bar.sync 1, 256;" ::: "memory");   // producers only (threads 256..511)
}

__device__ __forceinline__ void mbar_init(uint32_t addr, uint32_t cnt) {
    asm volatile("mbarrier.init.shared.b64 [%0], %1;" :: "r"(addr), "r"(cnt) : "memory");
}
__device__ __forceinline__ void mbar_arrive(uint32_t addr) {
    asm volatile("mbarrier.arrive.shared.b64 _, [%0];" :: "r"(addr) : "memory");
}
__device__ __forceinline__ void mbar_wait(uint32_t addr, uint32_t ph) {
    asm volatile(
        "{\n\t.reg .pred P;\n"
        "W_%=:\n\t"
        "mbarrier.try_wait.parity.acquire.cta.shared::cta.b64 P, [%0], %1, 0x989680;\n\t"
        "@!P bra W_%=;\n\t}"
        :: "r"(addr), "r"(ph) : "memory");
}

__device__ __forceinline__ void ldm_x4(uint32_t& r0, uint32_t& r1, uint32_t& r2, uint32_t& r3,
                                       uint32_t addr) {
    asm volatile("ldmatrix.sync.aligned.m8n8.x4.shared.b16 {%0,%1,%2,%3}, [%4];"
                 : "=r"(r0), "=r"(r1), "=r"(r2), "=r"(r3) : "r"(addr));
}
__device__ __forceinline__ void mma16816(float& c0, float& c1, float& c2, float& c3,
                                         uint32_t a0, uint32_t a1, uint32_t a2, uint32_t a3,
                                         uint32_t b0, uint32_t b1) {
    asm volatile("mma.sync.aligned.m16n8k16.row.col.f32.f16.f16.f32 "
                 "{%0,%1,%2,%3}, {%4,%5,%6,%7}, {%8,%9}, {%0,%1,%2,%3};"
                 : "+f"(c0), "+f"(c1), "+f"(c2), "+f"(c3)
                 : "r"(a0), "r"(a1), "r"(a2), "r"(a3), "r"(b0), "r"(b1));
}

// magic-number fp16 pair: u = 0x6400|v ; (u - off) * s
__device__ __forceinline__ uint32_t dq2(uint32_t bits, uint32_t off, uint32_t s2) {
    uint32_t u = 0x64006400u | bits;
    __half2 h = __hsub2(*reinterpret_cast<__half2*>(&u),
                        *reinterpret_cast<const __half2*>(&off));
    h = __hmul2(h, *reinterpret_cast<const __half2*>(&s2));
    return *reinterpret_cast<uint32_t*>(&h);
}

// ---------------- prep: x_perm -> fp16 (ILP 4) ----------------
__global__ void prep_kernel(const float* __restrict__ x, const int* __restrict__ ci) {
    int t = blockIdx.x * blockDim.x + threadIdx.x;   // 65536 threads, 4 k each
    int m = t >> 10;
    int k4 = (t & 1023) << 2;
    const int4 c4 = *(const int4*)(ci + k4);
    const float* xr = x + (m << 12);
    float f0 = xr[c4.x], f1 = xr[c4.y], f2 = xr[c4.z], f3 = xr[c4.w];
    __half2 h01 = __floats2half2_rn(f0, f1);
    __half2 h23 = __floats2half2_rn(f2, f3);
    uint2 v;
    v.x = *reinterpret_cast<uint32_t*>(&h01);
    v.y = *reinterpret_cast<uint32_t*>(&h23);
    *(uint2*)(g_xp + (m << 12) + k4) = v;
}

// ---------------- reduce: out = out + part + bias ----------------
__global__ void reduce_kernel(float* __restrict__ out, const float* __restrict__ bias) {
    int n = blockIdx.x * blockDim.x + threadIdx.x;
    int m = blockIdx.y;
    int i = m * N_OUT + n;
    out[i] = out[i] + g_part[i] + bias[n];
}

// ---------------- warp-specialized dequant + mma.sync GEMM (split-K 2) ----------------
__global__ void __launch_bounds__(THREADS, 2) gemm_kernel(
    const int* __restrict__ Wh, const int* __restrict__ Wl,
    const float* __restrict__ sh, const float* __restrict__ sl,
    float* __restrict__ out)
{
    extern __shared__ char smem[];
    const uint32_t sb = smem_u32(smem);
    const int tid = threadIdx.x;
    const int n0 = blockIdx.x * NT;
    const int kh = blockIdx.y;
    const int cbase = kh * CPC;

    const int lane = tid & 31;
    const int wid  = tid >> 5;

    if (tid == 0) {
        #pragma unroll
        for (int s = 0; s < 3; ++s) {
            mbar_init(sb + MBAR + s * 8, 256);        // full[s]: 256 producers
            mbar_init(sb + MBAR + 24 + s * 8, 256);   // empty[s]: 256 consumers
        }
    }
    __syncthreads();

    if (wid < 8) {
        // ================= CONSUMER =================
        const int wm = wid & 3;
        const int wn = wid >> 2;
        const int sub = lane >> 3;
        const uint32_t offA  = (uint32_t)((wm * 16 + (sub & 1) * 8 + (lane & 7)) * 128 + (sub >> 1) * 16);
        const uint32_t offB0 = (uint32_t)((wn * 32 + (sub >> 1) * 8 + (lane & 7)) * 128 + (sub & 1) * 16);
        const uint32_t offB1 = offB0 + 16 * 128;

        float acc[4][4];
        #pragma unroll
        for (int j = 0; j < 4; ++j)
            #pragma unroll
            for (int i = 0; i < 4; ++i) acc[j][i] = 0.0f;

        int stage = 0, phase = 0;
        for (int c = 0; c < CPC; ++c) {
            mbar_wait(sb + MBAR + stage * 8, phase);          // full[stage]
            const uint32_t ab = sb + (uint32_t)(stage * ABST);
            #pragma unroll
            for (int ks = 0; ks < 4; ++ks) {
                uint32_t a0, a1, a2, a3, b0, b1, b2, b3;
                ldm_x4(a0, a1, a2, a3, ab + swz(offA + (uint32_t)(ks * 32)));
                ldm_x4(b0, b1, b2, b3, ab + 8192 + swz(offB0 + (uint32_t)(ks * 32)));
                mma16816(acc[0][0], acc[0][1], acc[0][2], acc[0][3], a0, a1, a2, a3, b0, b1);
                mma16816(acc[1][0], acc[1][1], acc[1][2], acc[1][3], a0, a1, a2, a3, b2, b3);
                ldm_x4(b0, b1, b2, b3, ab + 8192 + swz(offB1 + (uint32_t)(ks * 32)));
                mma16816(acc[2][0], acc[2][1], acc[2][2], acc[2][3], a0, a1, a2, a3, b0, b1);
                mma16816(acc[3][0], acc[3][1], acc[3][2], acc[3][3], a0, a1, a2, a3, b2, b3);
            }
            mbar_arrive(sb + MBAR + 24 + stage * 8);          // empty[stage]
            if (++stage == 3) { stage = 0; phase ^= 1; }
        }

        // epilogue: partials -> out (kh=0) or g_part (kh=1)
        float* dst = kh ? g_part : out;
        const int r0 = wm * 16 + (lane >> 2);
        #pragma unroll
        for (int j = 0; j < 4; ++j) {
            const int nb = n0 + wn * 32 + (j >> 1) * 16 + (j & 1) * 8 + (lane & 3) * 2;
            float2 o;
            o.x = acc[j][0];
            o.y = acc[j][1];
            *(float2*)(dst + r0 * N_OUT + nb) = o;
            o.x = acc[j][2];
            o.y = acc[j][3];
            *(float2*)(dst + (r0 + 8) * N_OUT + nb) = o;
        }
    } else {
        // ================= PRODUCER =================
        const int ptid = tid - 256;     // 0..255
        const int bn = ptid & 63;       // dequant column
        const int gq = ptid >> 6;       // 0..3

        auto issue = [&](int cf) {
            const int cg = cbase + cf;
            const int k0 = cg * KC;
            const uint32_t slotAB = sb + (uint32_t)((cf % 3) * ABST);
            const uint32_t slotR  = sb + RAW0 + (uint32_t)((cf % 3) * RAWST);
            // A: 2 granules of 16B per thread, pre-swizzled
            {
                int g = ptid;
                cp16(slotAB + swz((uint32_t)((g >> 3) * 128 + (g & 7) * 16)),
                     g_xp + ((g >> 3) << 12) + k0 + ((g & 7) << 3));
                g = ptid + 256;
                cp16(slotAB + swz((uint32_t)((g >> 3) * 128 + (g & 7) * 16)),
                     g_xp + ((g >> 3) << 12) + k0 + ((g & 7) << 3));
            }
            if (cg < 16) {
                const int* src = Wh + 48 * cg * N_OUT + n0;
                #pragma unroll
                for (int b = 0; b < 3; ++b) {
                    int g = ptid + b * 256;
                    cp16(slotR + (g >> 4) * 256 + (g & 15) * 16,
                         src + (g >> 4) * N_OUT + (g & 15) * 4);
                }
                if (ptid < 16)
                    cp16(slotR + 12288 + ptid * 16, sh + (k0 >> 7) * N_OUT + n0 + ptid * 4);
            } else {
                const int* src = Wl + 40 * (cg - 16) * N_OUT + n0;
                #pragma unroll
                for (int b = 0; b < 2; ++b) {
                    int g = ptid + b * 256;
                    cp16(slotR + (g >> 4) * 256 + (g & 15) * 16,
                         src + (g >> 4) * N_OUT + (g & 15) * 4);
                }
                if (ptid < 128) {
                    int g = ptid + 512;
                    cp16(slotR + (g >> 4) * 256 + (g & 15) * 16,
                         src + (g >> 4) * N_OUT + (g & 15) * 4);
                }
                if (ptid < 16)
                    cp16(slotR + 12288 + ptid * 16,
                         sl + ((k0 - HIGH_K) >> 7) * N_OUT + n0 + ptid * 4);
            }
        };

        // prologue: stages 0,1 (empty waits pass immediately: parity 1 on fresh barrier)
        mbar_wait(sb + MBAR + 24 + 0, 1);
        issue(0); cp_commit();
        mbar_wait(sb + MBAR + 24 + 8, 1);
        issue(1); cp_commit();

        int dstage = 0;                   // dequant cursor (stage c%3)
        int istage = 2, iphase = 0;       // issue cursor for cf=c+2; empty parity = iphase^1
        for (int c = 0; c < CPC; ++c) {
            if (c + 2 < CPC) {
                mbar_wait(sb + MBAR + 24 + istage * 8, iphase ^ 1);
                issue(c + 2);
                if (++istage == 3) { istage = 0; iphase ^= 1; }
            }
            cp_commit();
            cp_wait2();
            // cross-thread visibility: wait_group only covers THIS thread's
            // copies; dequant reads rows staged by other producer threads.
            prod_bar();

            const int cg = cbase + c;
            const uint32_t bdst = (uint32_t)(dstage * ABST) + 8192;
            const int* wp = (const int*)(smem + (RAW0 + dstage * RAWST));
            const float sf = *(const float*)(smem + (RAW0 + dstage * RAWST + 12288) + bn * 4);
            const __half sh1 = __float2half_rn(sf);
            const __half2 sh2v = __half2half2(sh1);
            const uint32_t s2 = *reinterpret_cast<const uint32_t*>(&sh2v);

            if (cg < 16) {   // 6-bit: 4 quads per thread
                #pragma unroll
                for (int qq = 0; qq < 4; ++qq) {
                    const int qi = gq + qq * 4;
                    const int rb = 3 * qi;
                    int w0 = wp[(rb + 0) * 64 + bn];
                    int w1 = wp[(rb + 1) * 64 + bn];
                    int w2 = wp[(rb + 2) * 64 + bn];
                    uint32_t b01 = (w0 & 63) | ((w0 & 0xC0) << 10) | ((w1 & 15) << 18);
                    uint32_t b23 = ((w1 >> 4) & 15) | ((w2 & 3) << 4) | ((w2 & 0xFC) << 14);
                    uint2 val;
                    val.x = dq2(b01, 0x641F641Fu, s2);
                    val.y = dq2(b23, 0x641F641Fu, s2);
                    *(uint2*)(smem + bdst + swz((uint32_t)(bn * 128 + qi * 8))) = val;
                }
            } else {         // 5-bit: 2 octets per thread
                #pragma unroll
                for (int oo = 0; oo < 2; ++oo) {
                    const int oi = gq + oo * 4;
                    const int rb = 5 * oi;
                    int w0 = wp[(rb + 0) * 64 + bn];
                    int w1 = wp[(rb + 1) * 64 + bn];
                    int w2 = wp[(rb + 2) * 64 + bn];
                    int w3 = wp[(rb + 3) * 64 + bn];
                    int w4 = wp[(rb + 4) * 64 + bn];
                    uint32_t b01 = (w0 & 31) | ((w0 & 0xE0) << 11) | ((w1 & 3) << 19);
                    uint32_t b23 = ((w1 >> 2) & 31) | ((w1 & 0x80) << 9) | ((w2 & 15) << 17);
                    uint32_t b45 = ((w2 >> 4) & 15) | ((w3 & 1) << 4) | ((w3 & 0x3E) << 15);
                    uint32_t b67 = ((w3 >> 6) & 3) | ((w4 & 7) << 2) | ((w4 & 0xF8) << 13);
                    uint4 val;
                    val.x = dq2(b01, 0x640F640Fu, s2);
                    val.y = dq2(b23, 0x640F640Fu, s2);
                    val.z = dq2(b45, 0x640F640Fu, s2);
                    val.w = dq2(b67, 0x640F640Fu, s2);
                    *(uint4*)(smem + bdst + swz((uint32_t)(bn * 128 + oi * 16))) = val;
                }
            }
            mbar_arrive(sb + MBAR + dstage * 8);     // full[dstage]
            if (++dstage == 3) dstage = 0;
        }
    }
}

extern "C" void kernel_launch(void* const* d_in, const int* in_sizes, int n_in,
                              void* d_out, int out_size) {
    const float* x    = (const float*)d_in[0];
    const int*   Wh   = (const int*)d_in[1];
    const int*   Wl   = (const int*)d_in[2];
    const float* sh   = (const float*)d_in[3];
    const float* sl   = (const float*)d_in[4];
    const int*   ci   = (const int*)d_in[5];
    const float* bias = (const float*)d_in[6];
    float* out = (float*)d_out;

    cudaFuncSetAttribute(gemm_kernel, cudaFuncAttributeMaxDynamicSharedMemorySize, SMEM_BYTES);

    prep_kernel<<<(M_TOK * K_TOT / 4) / 256, 256>>>(x, ci);
    gemm_kernel<<<dim3(N_OUT / NT, 2), THREADS, SMEM_BYTES>>>(Wh, Wl, sh, sl, out);
    reduce_kernel<<<dim3(N_OUT / 256, M_TOK), 256>>>(out, bias);
}

// round 10
// speedup vs baseline: 1.3910x; 1.0420x over previous
#include <cuda_runtime.h>
#include <cuda_fp16.h>
#include <stdint.h>

#define N_OUT  11008
#define K_TOT  4096
#define M_TOK  64
#define HIGH_K 1024
#define NT     64      // output columns per CTA
#define KC     64      // K per chunk
#define CPC    32      // chunks per CTA (split-K = 2)
#define THREADS 512

// SMEM layout
//   A ring:   3 x 8192   @ 0       (fp16, pre-swizzled, consumer-staged)
//   B ring:   4 x 8192   @ 24576   (fp16, swizzled, producer-dequanted)
//   RAW ring: 3 x 12544  @ 57344   (packed W 12288 + scales 256)
//   mbar:     full[4], empty[4] @ 94976
#define ASTG  8192
#define BR0   24576
#define RAW0  57344
#define RAWST 12544
#define MBAR  94976
#define SMEM_BYTES 95040

__device__ __half g_xp[M_TOK * K_TOT];     // permuted x in fp16 (512KB)
__device__ float  g_part[M_TOK * N_OUT];   // split-K partial (2.8MB)

__device__ __forceinline__ uint32_t smem_u32(const void* p) {
    uint32_t a;
    asm("{ .reg .u64 t; cvta.to.shared.u64 t, %1; cvt.u32.u64 %0, t; }" : "=r"(a) : "l"(p));
    return a;
}
__device__ __forceinline__ uint32_t swz(uint32_t o) { return o ^ ((o >> 3) & 0x70); }

__device__ __forceinline__ void cp16(uint32_t dst, const void* src) {
    asm volatile("cp.async.cg.shared.global [%0], [%1], 16;" :: "r"(dst), "l"(src));
}
__device__ __forceinline__ void cp_commit() {
    asm volatile("cp.async.commit_group;" ::: "memory");
}
__device__ __forceinline__ void cp_wait1() {
    asm volatile("cp.async.wait_group 1;" ::: "memory");
}
__device__ __forceinline__ void cp_wait2g() {
    asm volatile("cp.async.wait_group 2;" ::: "memory");
}
__device__ __forceinline__ void prod_bar() {
    asm volatile("bar.sync 1, 256;" ::: "memory");   // producers (threads 256..511)
}
__device__ __forceinline__ void cons_bar() {
    asm volatile("bar.sync 2, 256;" ::: "memory");   // consumers (threads 0..255)
}

__device__ __forceinline__ void mbar_init(uint32_t addr, uint32_t cnt) {
    asm volatile("mbarrier.init.shared.b64 [%0], %1;" :: "r"(addr), "r"(cnt) : "memory");
}
__device__ __forceinline__ void mbar_arrive(uint32_t addr) {
    asm volatile("mbarrier.arrive.shared.b64 _, [%0];" :: "r"(addr) : "memory");
}
__device__ __forceinline__ void mbar_wait(uint32_t addr, uint32_t ph) {
    asm volatile(
        "{\n\t.reg .pred P;\n"
        "W_%=:\n\t"
        "mbarrier.try_wait.parity.acquire.cta.shared::cta.b64 P, [%0], %1, 0x989680;\n\t"
        "@!P bra W_%=;\n\t}"
        :: "r"(addr), "r"(ph) : "memory");
}

__device__ __forceinline__ void ldm_x4(uint32_t& r0, uint32_t& r1, uint32_t& r2, uint32_t& r3,
                                       uint32_t addr) {
    asm volatile("ldmatrix.sync.aligned.m8n8.x4.shared.b16 {%0,%1,%2,%3}, [%4];"
                 : "=r"(r0), "=r"(r1), "=r"(r2), "=r"(r3) : "r"(addr));
}
__device__ __forceinline__ void mma16816(float& c0, float& c1, float& c2, float& c3,
                                         uint32_t a0, uint32_t a1, uint32_t a2, uint32_t a3,
                                         uint32_t b0, uint32_t b1) {
    asm volatile("mma.sync.aligned.m16n8k16.row.col.f32.f16.f16.f32 "
                 "{%0,%1,%2,%3}, {%4,%5,%6,%7}, {%8,%9}, {%0,%1,%2,%3};"
                 : "+f"(c0), "+f"(c1), "+f"(c2), "+f"(c3)
                 : "r"(a0), "r"(a1), "r"(a2), "r"(a3), "r"(b0), "r"(b1));
}

// magic-number fp16 pair: u = 0x6400|v ; (u - off) * s
__device__ __forceinline__ uint32_t dq2(uint32_t bits, uint32_t off, uint32_t s2) {
    uint32_t u = 0x64006400u | bits;
    __half2 h = __hsub2(*reinterpret_cast<__half2*>(&u),
                        *reinterpret_cast<const __half2*>(&off));
    h = __hmul2(h, *reinterpret_cast<const __half2*>(&s2));
    return *reinterpret_cast<uint32_t*>(&h);
}

// ---------------- prep: x_perm -> fp16 (1 elem/thread, max MLP) ----------------
__global__ void prep_kernel(const float* __restrict__ x, const int* __restrict__ ci) {
    int idx = blockIdx.x * blockDim.x + threadIdx.x;   // 262144 threads
    int m = idx >> 12;
    int k = idx & 4095;
    g_xp[idx] = __float2half_rn(x[(m << 12) + ci[k]]);
}

// ---------------- reduce: out = out + part + bias ----------------
__global__ void reduce_kernel(float* __restrict__ out, const float* __restrict__ bias) {
    int n = blockIdx.x * blockDim.x + threadIdx.x;
    int m = blockIdx.y;
    int i = m * N_OUT + n;
    out[i] = out[i] + g_part[i] + bias[n];
}

// ---------------- warp-specialized dequant + mma.sync GEMM (split-K 2) ----------------
__global__ void __launch_bounds__(THREADS, 2) gemm_kernel(
    const int* __restrict__ Wh, const int* __restrict__ Wl,
    const float* __restrict__ sh, const float* __restrict__ sl,
    float* __restrict__ out)
{
    extern __shared__ char smem[];
    const uint32_t sb = smem_u32(smem);
    const int tid = threadIdx.x;
    const int n0 = blockIdx.x * NT;
    const int kh = blockIdx.y;
    const int cbase = kh * CPC;

    const int lane = tid & 31;
    const int wid  = tid >> 5;

    if (tid == 0) {
        #pragma unroll
        for (int s = 0; s < 4; ++s) {
            mbar_init(sb + MBAR + s * 8, 256);        // full[s]
            mbar_init(sb + MBAR + 32 + s * 8, 256);   // empty[s]
        }
    }
    __syncthreads();

    if (wid < 8) {
        // ================= CONSUMER (threads 0..255) =================
        const int ctid = tid;
        const int wm = wid & 3;
        const int wn = wid >> 2;
        const int sub = lane >> 3;
        const uint32_t offA  = (uint32_t)((wm * 16 + (sub & 1) * 8 + (lane & 7)) * 128 + (sub >> 1) * 16);
        const uint32_t offB0 = (uint32_t)((wn * 32 + (sub >> 1) * 8 + (lane & 7)) * 128 + (sub & 1) * 16);
        const uint32_t offB1 = offB0 + 16 * 128;

        // self-staged A ring (depth 3), 2 granules per thread
        auto issueA = [&](int cf) {
            const int k0 = (cbase + cf) * KC;
            const uint32_t slot = sb + (uint32_t)((cf % 3) * ASTG);
            int g = ctid;
            cp16(slot + swz((uint32_t)((g >> 3) * 128 + (g & 7) * 16)),
                 g_xp + ((g >> 3) << 12) + k0 + ((g & 7) << 3));
            g = ctid + 256;
            cp16(slot + swz((uint32_t)((g >> 3) * 128 + (g & 7) * 16)),
                 g_xp + ((g >> 3) << 12) + k0 + ((g & 7) << 3));
        };

        float acc[4][4];
        #pragma unroll
        for (int j = 0; j < 4; ++j)
            #pragma unroll
            for (int i = 0; i < 4; ++i) acc[j][i] = 0.0f;

        issueA(0); cp_commit();
        issueA(1); cp_commit();

        for (int c = 0; c < CPC; ++c) {
            cons_bar();                       // all consumers done reading A[c-1]
            if (c + 2 < CPC) issueA(c + 2);   // safe: overwrites A[(c-1)%3] post-bar
            cp_commit();
            cp_wait2g();                      // own A(c) granules done
            cons_bar();                       // cross-thread visibility of A[c]

            mbar_wait(sb + MBAR + (c & 3) * 8, (c >> 2) & 1);   // B full
            const uint32_t ab = sb + (uint32_t)((c % 3) * ASTG);
            const uint32_t bb = sb + BR0 + (uint32_t)((c & 3) * 8192);
            #pragma unroll
            for (int ks = 0; ks < 4; ++ks) {
                uint32_t a0, a1, a2, a3, b0, b1, b2, b3;
                ldm_x4(a0, a1, a2, a3, ab + swz(offA + (uint32_t)(ks * 32)));
                ldm_x4(b0, b1, b2, b3, bb + swz(offB0 + (uint32_t)(ks * 32)));
                mma16816(acc[0][0], acc[0][1], acc[0][2], acc[0][3], a0, a1, a2, a3, b0, b1);
                mma16816(acc[1][0], acc[1][1], acc[1][2], acc[1][3], a0, a1, a2, a3, b2, b3);
                ldm_x4(b0, b1, b2, b3, bb + swz(offB1 + (uint32_t)(ks * 32)));
                mma16816(acc[2][0], acc[2][1], acc[2][2], acc[2][3], a0, a1, a2, a3, b0, b1);
                mma16816(acc[3][0], acc[3][1], acc[3][2], acc[3][3], a0, a1, a2, a3, b2, b3);
            }
            mbar_arrive(sb + MBAR + 32 + (c & 3) * 8);          // B empty
        }

        // epilogue: partials -> out (kh=0) or g_part (kh=1)
        float* dst = kh ? g_part : out;
        const int r0 = wm * 16 + (lane >> 2);
        #pragma unroll
        for (int j = 0; j < 4; ++j) {
            const int nb = n0 + wn * 32 + (j >> 1) * 16 + (j & 1) * 8 + (lane & 3) * 2;
            float2 o;
            o.x = acc[j][0];
            o.y = acc[j][1];
            *(float2*)(dst + r0 * N_OUT + nb) = o;
            o.x = acc[j][2];
            o.y = acc[j][3];
            *(float2*)(dst + (r0 + 8) * N_OUT + nb) = o;
        }
    } else {
        // ================= PRODUCER (threads 256..511) =================
        const int ptid = tid - 256;     // 0..255
        const int c2 = ptid & 31;       // 2-col group: cols 2c2, 2c2+1
        const int qp = ptid >> 5;       // quad-pair (6b) / octet (5b), 0..7

        auto issueW = [&](int cf) {
            const int cg = cbase + cf;
            const int k0 = cg * KC;
            const uint32_t slot = sb + RAW0 + (uint32_t)((cf % 3) * RAWST);
            if (cg < 16) {
                const int* src = Wh + 48 * cg * N_OUT + n0;
                #pragma unroll
                for (int b = 0; b < 3; ++b) {
                    int g = ptid + b * 256;
                    cp16(slot + (g >> 4) * 256 + (g & 15) * 16,
                         src + (g >> 4) * N_OUT + (g & 15) * 4);
                }
                if (ptid < 16)
                    cp16(slot + 12288 + ptid * 16, sh + (k0 >> 7) * N_OUT + n0 + ptid * 4);
            } else {
                const int* src = Wl + 40 * (cg - 16) * N_OUT + n0;
                #pragma unroll
                for (int b = 0; b < 2; ++b) {
                    int g = ptid + b * 256;
                    cp16(slot + (g >> 4) * 256 + (g & 15) * 16,
                         src + (g >> 4) * N_OUT + (g & 15) * 4);
                }
                if (ptid < 128) {
                    int g = ptid + 512;
                    cp16(slot + (g >> 4) * 256 + (g & 15) * 16,
                         src + (g >> 4) * N_OUT + (g & 15) * 4);
                }
                if (ptid < 16)
                    cp16(slot + 12288 + ptid * 16,
                         sl + ((k0 - HIGH_K) >> 7) * N_OUT + n0 + ptid * 4);
            }
        };

        issueW(0); cp_commit();
        issueW(1); cp_commit();

        for (int c = 0; c < CPC; ++c) {
            cp_wait1();          // own W(c) group complete
            prod_bar();          // all producers: W(c) visible, dequant(c-1) finished
            if (c + 2 < CPC) issueW(c + 2);   // safe: overwrites raw[(c-1)%3] post-bar
            cp_commit();

            const int cg = cbase + c;
            const char* rawp = smem + RAW0 + (c % 3) * RAWST;
            const float2 sc = *(const float2*)(rawp + 12288 + c2 * 8);
            const uint32_t bb = BR0 + (uint32_t)((c & 3) * 8192);

            // B-slot free?
            mbar_wait(sb + MBAR + 32 + (c & 3) * 8, ((c >> 2) & 1) ^ 1);

            if (cg < 16) {   // 6-bit: 2 cols x quads {2qp, 2qp+1}
                int2 r[6];
                #pragma unroll
                for (int j = 0; j < 6; ++j)
                    r[j] = *(const int2*)(rawp + (6 * qp + j) * 256 + c2 * 8);
                #pragma unroll
                for (int cc = 0; cc < 2; ++cc) {
                    const float sf = cc ? sc.y : sc.x;
                    const __half2 sh2v = __half2half2(__float2half_rn(sf));
                    const uint32_t s2 = *reinterpret_cast<const uint32_t*>(&sh2v);
                    int w0 = cc ? r[0].y : r[0].x;
                    int w1 = cc ? r[1].y : r[1].x;
                    int w2 = cc ? r[2].y : r[2].x;
                    int w3 = cc ? r[3].y : r[3].x;
                    int w4 = cc ? r[4].y : r[4].x;
                    int w5 = cc ? r[5].y : r[5].x;
                    uint4 val;
                    val.x = dq2((w0 & 63) | ((w0 & 0xC0) << 10) | ((w1 & 15) << 18), 0x641F641Fu, s2);
                    val.y = dq2(((w1 >> 4) & 15) | ((w2 & 3) << 4) | ((w2 & 0xFC) << 14), 0x641F641Fu, s2);
                    val.z = dq2((w3 & 63) | ((w3 & 0xC0) << 10) | ((w4 & 15) << 18), 0x641F641Fu, s2);
                    val.w = dq2(((w4 >> 4) & 15) | ((w5 & 3) << 4) | ((w5 & 0xFC) << 14), 0x641F641Fu, s2);
                    *(uint4*)(smem + bb + swz((uint32_t)((2 * c2 + cc) * 128 + qp * 16))) = val;
                }
            } else {         // 5-bit: 2 cols x octet qp
                int2 r[5];
                #pragma unroll
                for (int j = 0; j < 5; ++j)
                    r[j] = *(const int2*)(rawp + (5 * qp + j) * 256 + c2 * 8);
                #pragma unroll
                for (int cc = 0; cc < 2; ++cc) {
                    const float sf = cc ? sc.y : sc.x;
                    const __half2 sh2v = __half2half2(__float2half_rn(sf));
                    const uint32_t s2 = *reinterpret_cast<const uint32_t*>(&sh2v);
                    int w0 = cc ? r[0].y : r[0].x;
                    int w1 = cc ? r[1].y : r[1].x;
                    int w2 = cc ? r[2].y : r[2].x;
                    int w3 = cc ? r[3].y : r[3].x;
                    int w4 = cc ? r[4].y : r[4].x;
                    uint4 val;
                    val.x = dq2((w0 & 31) | ((w0 & 0xE0) << 11) | ((w1 & 3) << 19), 0x640F640Fu, s2);
                    val.y = dq2(((w1 >> 2) & 31) | ((w1 & 0x80) << 9) | ((w2 & 15) << 17), 0x640F640Fu, s2);
                    val.z = dq2(((w2 >> 4) & 15) | ((w3 & 1) << 4) | ((w3 & 0x3E) << 15), 0x640F640Fu, s2);
                    val.w = dq2(((w3 >> 6) & 3) | ((w4 & 7) << 2) | ((w4 & 0xF8) << 13), 0x640F640Fu, s2);
                    *(uint4*)(smem + bb + swz((uint32_t)((2 * c2 + cc) * 128 + qp * 16))) = val;
                }
            }
            mbar_arrive(sb + MBAR + (c & 3) * 8);     // B full
        }
    }
}

extern "C" void kernel_launch(void* const* d_in, const int* in_sizes, int n_in,
                              void* d_out, int out_size) {
    const float* x    = (const float*)d_in[0];
    const int*   Wh   = (const int*)d_in[1];
    const int*   Wl   = (const int*)d_in[2];
    const float* sh   = (const float*)d_in[3];
    const float* sl   = (const float*)d_in[4];
    const int*   ci   = (const int*)d_in[5];
    const float* bias = (const float*)d_in[6];
    float* out = (float*)d_out;

    cudaFuncSetAttribute(gemm_kernel, cudaFuncAttributeMaxDynamicSharedMemorySize, SMEM_BYTES);

    prep_kernel<<<(M_TOK * K_TOT) / 256, 256>>>(x, ci);
    gemm_kernel<<<dim3(N_OUT / NT, 2), THREADS, SMEM_BYTES>>>(Wh, Wl, sh, sl, out);
    reduce_kernel<<<dim3(N_OUT / 256, M_TOK), 256>>>(out, bias);
}

// round 11
// speedup vs baseline: 1.5504x; 1.1146x over previous
#include <cuda_runtime.h>
#include <cuda_fp16.h>
#include <stdint.h>

#define N_OUT  11008
#define K_TOT  4096
#define M_TOK  64
#define HIGH_K 1024
#define NT     64      // output columns per CTA
#define KC     64      // K per chunk
#define CPC    16      // chunks per CTA (split-K = 4)
#define NSPLIT 4
#define THREADS 512

// SMEM layout
//   A ring:   3 x 8192   @ 0       (fp16, pre-swizzled, consumer-staged)
//   B ring:   4 x 8192   @ 24576   (fp16, swizzled, producer-dequanted)
//   RAW ring: 3 x 12544  @ 57344   (packed W 12288 + scales 256)
//   mbar:     full[4], empty[4] @ 94976
#define ASTG  8192
#define BR0   24576
#define RAW0  57344
#define RAWST 12544
#define MBAR  94976
#define SMEM_BYTES 95040

__device__ __half g_xp[M_TOK * K_TOT];                    // permuted x fp16 (512KB)
__device__ float  g_part[(NSPLIT - 1) * M_TOK * N_OUT];   // split-K partials (8.4MB)

__device__ __forceinline__ uint32_t smem_u32(const void* p) {
    uint32_t a;
    asm("{ .reg .u64 t; cvta.to.shared.u64 t, %1; cvt.u32.u64 %0, t; }" : "=r"(a) : "l"(p));
    return a;
}
__device__ __forceinline__ uint32_t swz(uint32_t o) { return o ^ ((o >> 3) & 0x70); }

__device__ __forceinline__ void cp16(uint32_t dst, const void* src) {
    asm volatile("cp.async.cg.shared.global [%0], [%1], 16;" :: "r"(dst), "l"(src));
}
__device__ __forceinline__ void cp_commit() {
    asm volatile("cp.async.commit_group;" ::: "memory");
}
__device__ __forceinline__ void cp_wait1() {
    asm volatile("cp.async.wait_group 1;" ::: "memory");
}
__device__ __forceinline__ void cp_wait2g() {
    asm volatile("cp.async.wait_group 2;" ::: "memory");
}
__device__ __forceinline__ void prod_bar() {
    asm volatile("bar.sync 1, 256;" ::: "memory");   // producers (threads 256..511)
}
__device__ __forceinline__ void cons_bar() {
    asm volatile("bar.sync 2, 256;" ::: "memory");   // consumers (threads 0..255)
}

__device__ __forceinline__ void mbar_init(uint32_t addr, uint32_t cnt) {
    asm volatile("mbarrier.init.shared.b64 [%0], %1;" :: "r"(addr), "r"(cnt) : "memory");
}
__device__ __forceinline__ void mbar_arrive(uint32_t addr) {
    asm volatile("mbarrier.arrive.shared.b64 _, [%0];" :: "r"(addr) : "memory");
}
__device__ __forceinline__ void mbar_wait(uint32_t addr, uint32_t ph) {
    asm volatile(
        "{\n\t.reg .pred P;\n"
        "W_%=:\n\t"
        "mbarrier.try_wait.parity.acquire.cta.shared::cta.b64 P, [%0], %1, 0x989680;\n\t"
        "@!P bra W_%=;\n\t}"
        :: "r"(addr), "r"(ph) : "memory");
}

__device__ __forceinline__ void ldm_x4(uint32_t& r0, uint32_t& r1, uint32_t& r2, uint32_t& r3,
                                       uint32_t addr) {
    asm volatile("ldmatrix.sync.aligned.m8n8.x4.shared.b16 {%0,%1,%2,%3}, [%4];"
                 : "=r"(r0), "=r"(r1), "=r"(r2), "=r"(r3) : "r"(addr));
}
__device__ __forceinline__ void mma16816(float& c0, float& c1, float& c2, float& c3,
                                         uint32_t a0, uint32_t a1, uint32_t a2, uint32_t a3,
                                         uint32_t b0, uint32_t b1) {
    asm volatile("mma.sync.aligned.m16n8k16.row.col.f32.f16.f16.f32 "
                 "{%0,%1,%2,%3}, {%4,%5,%6,%7}, {%8,%9}, {%0,%1,%2,%3};"
                 : "+f"(c0), "+f"(c1), "+f"(c2), "+f"(c3)
                 : "r"(a0), "r"(a1), "r"(a2), "r"(a3), "r"(b0), "r"(b1));
}

// magic-number fp16 pair: u = 0x6400|v ; (u - off) * s
__device__ __forceinline__ uint32_t dq2(uint32_t bits, uint32_t off, uint32_t s2) {
    uint32_t u = 0x64006400u | bits;
    __half2 h = __hsub2(*reinterpret_cast<__half2*>(&u),
                        *reinterpret_cast<const __half2*>(&off));
    h = __hmul2(h, *reinterpret_cast<const __half2*>(&s2));
    return *reinterpret_cast<uint32_t*>(&h);
}

// ---------------- prep: x_perm -> fp16 (2 rows per thread, ci reuse) ----------------
__global__ void prep_kernel(const float* __restrict__ x, const int* __restrict__ ci) {
    int t = blockIdx.x * blockDim.x + threadIdx.x;   // 131072 threads
    int m = t >> 12;                                 // 0..31
    int k = t & 4095;
    int c = ci[k];
    g_xp[(m << 12) + k]            = __float2half_rn(x[(m << 12) + c]);
    g_xp[((m + 32) << 12) + k]     = __float2half_rn(x[((m + 32) << 12) + c]);
}

// ---------------- reduce: out = out + 3 partials + bias ----------------
__global__ void reduce_kernel(float* __restrict__ out, const float* __restrict__ bias) {
    int n = blockIdx.x * blockDim.x + threadIdx.x;
    int m = blockIdx.y;
    int i = m * N_OUT + n;
    out[i] = out[i] + g_part[i] + g_part[i + M_TOK * N_OUT]
                    + g_part[i + 2 * M_TOK * N_OUT] + bias[n];
}

// ---------------- warp-specialized dequant + mma.sync GEMM (split-K 4) ----------------
__global__ void __launch_bounds__(THREADS, 2) gemm_kernel(
    const int* __restrict__ Wh, const int* __restrict__ Wl,
    const float* __restrict__ sh, const float* __restrict__ sl,
    float* __restrict__ out)
{
    extern __shared__ char smem[];
    const uint32_t sb = smem_u32(smem);
    const int tid = threadIdx.x;
    const int n0 = blockIdx.x * NT;
    const int kh = blockIdx.y;          // 0..3; kh=0 is pure 6-bit, kh>=1 pure 5-bit
    const int cbase = kh * CPC;

    const int lane = tid & 31;
    const int wid  = tid >> 5;

    if (tid == 0) {
        #pragma unroll
        for (int s = 0; s < 4; ++s) {
            mbar_init(sb + MBAR + s * 8, 256);        // full[s]
            mbar_init(sb + MBAR + 32 + s * 8, 256);   // empty[s]
        }
    }
    __syncthreads();

    if (wid < 8) {
        // ================= CONSUMER (threads 0..255) =================
        const int ctid = tid;
        const int wm = wid & 3;
        const int wn = wid >> 2;
        const int sub = lane >> 3;
        const uint32_t offA  = (uint32_t)((wm * 16 + (sub & 1) * 8 + (lane & 7)) * 128 + (sub >> 1) * 16);
        const uint32_t offB0 = (uint32_t)((wn * 32 + (sub >> 1) * 8 + (lane & 7)) * 128 + (sub & 1) * 16);
        const uint32_t offB1 = offB0 + 16 * 128;

        auto issueA = [&](int cf) {
            const int k0 = (cbase + cf) * KC;
            const uint32_t slot = sb + (uint32_t)((cf % 3) * ASTG);
            int g = ctid;
            cp16(slot + swz((uint32_t)((g >> 3) * 128 + (g & 7) * 16)),
                 g_xp + ((g >> 3) << 12) + k0 + ((g & 7) << 3));
            g = ctid + 256;
            cp16(slot + swz((uint32_t)((g >> 3) * 128 + (g & 7) * 16)),
                 g_xp + ((g >> 3) << 12) + k0 + ((g & 7) << 3));
        };

        float acc[4][4];
        #pragma unroll
        for (int j = 0; j < 4; ++j)
            #pragma unroll
            for (int i = 0; i < 4; ++i) acc[j][i] = 0.0f;

        issueA(0); cp_commit();
        issueA(1); cp_commit();

        for (int c = 0; c < CPC; ++c) {
            cons_bar();                       // all consumers done reading A[c-1]
            if (c + 2 < CPC) issueA(c + 2);   // overwrites A[(c-1)%3] post-bar
            cp_commit();
            cp_wait2g();                      // own A(c) granules done
            cons_bar();                       // cross-thread visibility of A[c]

            mbar_wait(sb + MBAR + (c & 3) * 8, (c >> 2) & 1);   // B full
            const uint32_t ab = sb + (uint32_t)((c % 3) * ASTG);
            const uint32_t bb = sb + BR0 + (uint32_t)((c & 3) * 8192);
            #pragma unroll
            for (int ks = 0; ks < 4; ++ks) {
                uint32_t a0, a1, a2, a3, b0, b1, b2, b3;
                ldm_x4(a0, a1, a2, a3, ab + swz(offA + (uint32_t)(ks * 32)));
                ldm_x4(b0, b1, b2, b3, bb + swz(offB0 + (uint32_t)(ks * 32)));
                mma16816(acc[0][0], acc[0][1], acc[0][2], acc[0][3], a0, a1, a2, a3, b0, b1);
                mma16816(acc[1][0], acc[1][1], acc[1][2], acc[1][3], a0, a1, a2, a3, b2, b3);
                ldm_x4(b0, b1, b2, b3, bb + swz(offB1 + (uint32_t)(ks * 32)));
                mma16816(acc[2][0], acc[2][1], acc[2][2], acc[2][3], a0, a1, a2, a3, b0, b1);
                mma16816(acc[3][0], acc[3][1], acc[3][2], acc[3][3], a0, a1, a2, a3, b2, b3);
            }
            mbar_arrive(sb + MBAR + 32 + (c & 3) * 8);          // B empty
        }

        // epilogue: kh=0 -> out, kh>=1 -> g_part[kh-1]
        float* dst = (kh == 0) ? out : (g_part + (kh - 1) * M_TOK * N_OUT);
        const int r0 = wm * 16 + (lane >> 2);
        #pragma unroll
        for (int j = 0; j < 4; ++j) {
            const int nb = n0 + wn * 32 + (j >> 1) * 16 + (j & 1) * 8 + (lane & 3) * 2;
            float2 o;
            o.x = acc[j][0];
            o.y = acc[j][1];
            *(float2*)(dst + r0 * N_OUT + nb) = o;
            o.x = acc[j][2];
            o.y = acc[j][3];
            *(float2*)(dst + (r0 + 8) * N_OUT + nb) = o;
        }
    } else {
        // ================= PRODUCER (threads 256..511) =================
        const int ptid = tid - 256;     // 0..255
        const int c2 = ptid & 31;       // 2-col group: cols 2c2, 2c2+1
        const int qp = ptid >> 5;       // quad-pair (6b) / octet (5b), 0..7

        auto issueW = [&](int cf) {
            const int cg = cbase + cf;
            const int k0 = cg * KC;
            const uint32_t slot = sb + RAW0 + (uint32_t)((cf % 3) * RAWST);
            if (cg < 16) {
                const int* src = Wh + 48 * cg * N_OUT + n0;
                #pragma unroll
                for (int b = 0; b < 3; ++b) {
                    int g = ptid + b * 256;
                    cp16(slot + (g >> 4) * 256 + (g & 15) * 16,
                         src + (g >> 4) * N_OUT + (g & 15) * 4);
                }
                if (ptid < 16)
                    cp16(slot + 12288 + ptid * 16, sh + (k0 >> 7) * N_OUT + n0 + ptid * 4);
            } else {
                const int* src = Wl + 40 * (cg - 16) * N_OUT + n0;
                #pragma unroll
                for (int b = 0; b < 2; ++b) {
                    int g = ptid + b * 256;
                    cp16(slot + (g >> 4) * 256 + (g & 15) * 16,
                         src + (g >> 4) * N_OUT + (g & 15) * 4);
                }
                if (ptid < 128) {
                    int g = ptid + 512;
                    cp16(slot + (g >> 4) * 256 + (g & 15) * 16,
                         src + (g >> 4) * N_OUT + (g & 15) * 4);
                }
                if (ptid < 16)
                    cp16(slot + 12288 + ptid * 16,
                         sl + ((k0 - HIGH_K) >> 7) * N_OUT + n0 + ptid * 4);
            }
        };

        issueW(0); cp_commit();
        issueW(1); cp_commit();

        for (int c = 0; c < CPC; ++c) {
            cp_wait1();          // own W(c) group complete
            prod_bar();          // all producers: W(c) visible, dequant(c-1) finished
            if (c + 2 < CPC) issueW(c + 2);   // overwrites raw[(c-1)%3] post-bar
            cp_commit();

            const int cg = cbase + c;
            const char* rawp = smem + RAW0 + (c % 3) * RAWST;
            const float2 sc = *(const float2*)(rawp + 12288 + c2 * 8);
            const uint32_t bb = BR0 + (uint32_t)((c & 3) * 8192);

            mbar_wait(sb + MBAR + 32 + (c & 3) * 8, ((c >> 2) & 1) ^ 1);   // B empty

            if (cg < 16) {   // 6-bit: 2 cols x quads {2qp, 2qp+1}
                int2 r[6];
                #pragma unroll
                for (int j = 0; j < 6; ++j)
                    r[j] = *(const int2*)(rawp + (6 * qp + j) * 256 + c2 * 8);
                #pragma unroll
                for (int cc = 0; cc < 2; ++cc) {
                    const float sf = cc ? sc.y : sc.x;
                    const __half2 sh2v = __half2half2(__float2half_rn(sf));
                    const uint32_t s2 = *reinterpret_cast<const uint32_t*>(&sh2v);
                    int w0 = cc ? r[0].y : r[0].x;
                    int w1 = cc ? r[1].y : r[1].x;
                    int w2 = cc ? r[2].y : r[2].x;
                    int w3 = cc ? r[3].y : r[3].x;
                    int w4 = cc ? r[4].y : r[4].x;
                    int w5 = cc ? r[5].y : r[5].x;
                    uint4 val;
                    val.x = dq2((w0 & 63) | ((w0 & 0xC0) << 10) | ((w1 & 15) << 18), 0x641F641Fu, s2);
                    val.y = dq2(((w1 >> 4) & 15) | ((w2 & 3) << 4) | ((w2 & 0xFC) << 14), 0x641F641Fu, s2);
                    val.z = dq2((w3 & 63) | ((w3 & 0xC0) << 10) | ((w4 & 15) << 18), 0x641F641Fu, s2);
                    val.w = dq2(((w4 >> 4) & 15) | ((w5 & 3) << 4) | ((w5 & 0xFC) << 14), 0x641F641Fu, s2);
                    *(uint4*)(smem + bb + swz((uint32_t)((2 * c2 + cc) * 128 + qp * 16))) = val;
                }
            } else {         // 5-bit: 2 cols x octet qp
                int2 r[5];
                #pragma unroll
                for (int j = 0; j < 5; ++j)
                    r[j] = *(const int2*)(rawp + (5 * qp + j) * 256 + c2 * 8);
                #pragma unroll
                for (int cc = 0; cc < 2; ++cc) {
                    const float sf = cc ? sc.y : sc.x;
                    const __half2 sh2v = __half2half2(__float2half_rn(sf));
                    const uint32_t s2 = *reinterpret_cast<const uint32_t*>(&sh2v);
                    int w0 = cc ? r[0].y : r[0].x;
                    int w1 = cc ? r[1].y : r[1].x;
                    int w2 = cc ? r[2].y : r[2].x;
                    int w3 = cc ? r[3].y : r[3].x;
                    int w4 = cc ? r[4].y : r[4].x;
                    uint4 val;
                    val.x = dq2((w0 & 31) | ((w0 & 0xE0) << 11) | ((w1 & 3) << 19), 0x640F640Fu, s2);
                    val.y = dq2(((w1 >> 2) & 31) | ((w1 & 0x80) << 9) | ((w2 & 15) << 17), 0x640F640Fu, s2);
                    val.z = dq2(((w2 >> 4) & 15) | ((w3 & 1) << 4) | ((w3 & 0x3E) << 15), 0x640F640Fu, s2);
                    val.w = dq2(((w3 >> 6) & 3) | ((w4 & 7) << 2) | ((w4 & 0xF8) << 13), 0x640F640Fu, s2);
                    *(uint4*)(smem + bb + swz((uint32_t)((2 * c2 + cc) * 128 + qp * 16))) = val;
                }
            }
            mbar_arrive(sb + MBAR + (c & 3) * 8);     // B full
        }
    }
}

extern "C" void kernel_launch(void* const* d_in, const int* in_sizes, int n_in,
                              void* d_out, int out_size) {
    const float* x    = (const float*)d_in[0];
    const int*   Wh   = (const int*)d_in[1];
    const int*   Wl   = (const int*)d_in[2];
    const float* sh   = (const float*)d_in[3];
    const float* sl   = (const float*)d_in[4];
    const int*   ci   = (const int*)d_in[5];
    const float* bias = (const float*)d_in[6];
    float* out = (float*)d_out;

    cudaFuncSetAttribute(gemm_kernel, cudaFuncAttributeMaxDynamicSharedMemorySize, SMEM_BYTES);

    prep_kernel<<<(M_TOK / 2 * K_TOT) / 256, 256>>>(x, ci);
    gemm_kernel<<<dim3(N_OUT / NT, NSPLIT), THREADS, SMEM_BYTES>>>(Wh, Wl, sh, sl, out);
    reduce_kernel<<<dim3(N_OUT / 256, M_TOK), 256>>>(out, bias);
}